// round 1
// baseline (speedup 1.0000x reference)
#include <cuda_runtime.h>
#include <cuda_bf16.h>

// Dual marching cubes, GRID=192, ISO=0.
// Padded grid P is (194)^3 with pad value iso+1 = 1.0; cells are 193^3.
// Output (float32, concatenated, reference order):
//   verts  [193^3 * 3]   at V_OFF  = 0
//   vmask  [193^3]       at VM_OFF = 21,567,171
//   quads  [3*193*192*192*4] at Q_OFF = 28,756,228   (16B-aligned)
//   qmask  [3*193*192*192]   at QM_OFF = 114,133,252

#define GD   192
#define C    193            // cells per axis
#define NC   (C*C*C)        // 7,189,057 cells
#define NEX  (C*GD*GD)      // 7,114,752 edges per direction
#define NQ   (3*NEX)        // 21,344,256 quads
#define V_OFF  0
#define VM_OFF (3*NC)
#define Q_OFF  (VM_OFF + NC)
#define QM_OFF (Q_OFF + 4*NQ)

// P-coordinate sign: P[i,j,k] = grid[i-1,j-1,k-1] when 1<=i,j,k<=192, else +1.0 (sgn=false)
__device__ __forceinline__ bool sgnP(const float* __restrict__ g, int i, int j, int k) {
    if ((unsigned)(i - 1) < (unsigned)GD &&
        (unsigned)(j - 1) < (unsigned)GD &&
        (unsigned)(k - 1) < (unsigned)GD)
        return g[((i - 1) * GD + (j - 1)) * GD + (k - 1)] < 0.0f;
    return false;
}

__global__ void __launch_bounds__(256)
dmc_verts(const float* __restrict__ g, float* __restrict__ out)
{
    __shared__ float s[256 * 3];
    const int tid  = threadIdx.x;
    const int base = blockIdx.x * 256;
    int idx = base + tid;
    const bool active = idx < NC;
    int cidx = active ? idx : (NC - 1);   // clamp; clamped results land past guard

    // decompose: idx = (a*C + b)*C + c   (c fastest == z contiguous in grid)
    int c  = cidx % C;
    int t2 = cidx / C;
    int b  = t2 % C;
    int a  = t2 / C;

    // corner k: dx=k&1, dy=(k>>1)&1, dz=(k>>2)&1 ; grid coords (a+dx-1, b+dy-1, c+dz-1)
    float v[8];
    const int ga = a - 1, gb = b - 1, gc = c - 1;
    bool interior = (a >= 1) & (a <= GD - 1) & (b >= 1) & (b <= GD - 1) & (c >= 1) & (c <= GD - 1);
    if (interior) {
        const float* p = g + ((ga * GD + gb) * GD + gc);
        #pragma unroll
        for (int k = 0; k < 8; k++) {
            int dx = k & 1, dy = (k >> 1) & 1, dz = (k >> 2) & 1;
            v[k] = p[(dx * GD + dy) * GD + dz];
        }
    } else {
        #pragma unroll
        for (int k = 0; k < 8; k++) {
            int x = ga + (k & 1), y = gb + ((k >> 1) & 1), z = gc + ((k >> 2) & 1);
            bool in = ((unsigned)x < (unsigned)GD) & ((unsigned)y < (unsigned)GD) & ((unsigned)z < (unsigned)GD);
            v[k] = in ? g[(x * GD + y) * GD + z] : 1.0f;
        }
    }

    // 12 edges: A-corner, axis; B = A + (1<<axis). oa[axis] == 0 always.
    const int EA[12] = {0,2,4,6, 0,1,4,5, 0,1,2,3};
    float sx = 0.f, sy = 0.f, sz = 0.f, cnt = 0.f;
    #pragma unroll
    for (int e = 0; e < 12; e++) {
        int axis = e >> 2;
        int A = EA[e];
        int B = A + (1 << axis);
        float vA = v[A], vB = v[B];
        bool m = (vA < 0.0f) != (vB < 0.0f);
        if (m) {
            float tt = -vA / (vB - vA);
            float px = (axis == 0) ? tt : (float)(A & 1);
            float py = (axis == 1) ? tt : (float)((A >> 1) & 1);
            float pz = (axis == 2) ? tt : (float)((A >> 2) & 1);
            sx += px; sy += py; sz += pz; cnt += 1.0f;
        }
    }

    float inv = 1.0f / fmaxf(cnt, 1.0f);
    const float nrm = 1.0f / (float)(GD - 1);
    float fx = ((float)a + sx * inv - 1.0f) * nrm;
    float fy = ((float)b + sy * inv - 1.0f) * nrm;
    float fz = ((float)c + sz * inv - 1.0f) * nrm;

    // stage stride-3 writes through smem -> unit-stride coalesced stores
    s[tid * 3 + 0] = fx;
    s[tid * 3 + 1] = fy;
    s[tid * 3 + 2] = fz;
    __syncthreads();
    const int outb = base * 3;
    #pragma unroll
    for (int i = 0; i < 3; i++) {
        int o = outb + tid + i * 256;
        if (o < 3 * NC) out[V_OFF + o] = s[tid + i * 256];
    }
    if (active) out[VM_OFF + idx] = (cnt > 0.0f) ? 1.0f : 0.0f;
}

__device__ __forceinline__ float fcid(int x, int y, int z) {
    return (float)((x * C + y) * C + z);   // < 193^3 < 2^24, exact in fp32
}

__global__ void __launch_bounds__(256)
dmc_quads(const float* __restrict__ g, float* __restrict__ out)
{
    int idx = blockIdx.x * 256 + threadIdx.x;
    if (idx >= NQ) return;

    int dir = idx / NEX;
    int r   = idx - dir * NEX;

    bool m;
    float4 q;
    if (dir == 0) {
        // x-edges: shape (193, 192, 192) over (a, b-1, c-1); b,c in [1,192]
        int a   = r / (GD * GD);
        int rem = r - a * (GD * GD);
        int b   = rem / GD + 1;
        int c   = rem % GD + 1;
        m = sgnP(g, a, b, c) != sgnP(g, a + 1, b, c);
        q = make_float4(fcid(a, b - 1, c - 1), fcid(a, b, c - 1), fcid(a, b, c), fcid(a, b - 1, c));
    } else if (dir == 1) {
        // y-edges: shape (192, 193, 192) over (a-1, b, c-1); a,c in [1,192]
        int a   = r / (C * GD) + 1;
        int rem = r % (C * GD);
        int b   = rem / GD;
        int c   = rem % GD + 1;
        m = sgnP(g, a, b, c) != sgnP(g, a, b + 1, c);
        q = make_float4(fcid(a - 1, b, c - 1), fcid(a, b, c - 1), fcid(a, b, c), fcid(a - 1, b, c));
    } else {
        // z-edges: shape (192, 192, 193) over (a-1, b-1, c); a,b in [1,192]
        int a   = r / (GD * C) + 1;
        int rem = r % (GD * C);
        int b   = rem / C + 1;
        int c   = rem % C;
        m = sgnP(g, a, b, c) != sgnP(g, a, b, c + 1);
        q = make_float4(fcid(a - 1, b - 1, c), fcid(a, b - 1, c), fcid(a, b, c), fcid(a - 1, b, c));
    }

    ((float4*)(out + Q_OFF))[idx] = q;
    out[QM_OFF + idx] = m ? 1.0f : 0.0f;
}

extern "C" void kernel_launch(void* const* d_in, const int* in_sizes, int n_in,
                              void* d_out, int out_size)
{
    const float* g = (const float*)d_in[0];
    float* out = (float*)d_out;

    dmc_verts<<<(NC + 255) / 256, 256>>>(g, out);
    dmc_quads<<<(NQ + 255) / 256, 256>>>(g, out);
}